// round 1
// baseline (speedup 1.0000x reference)
#include <cuda_runtime.h>
#include <cuda_bf16.h>

// Problem shape (fixed by the dataset):
//   x : [16, 512, 64, 64] f32
//   s : [16, 512, 1, 4096] f32
//   z : [16, 1, 512, 1]   f32
//   wq: [1,1,5], wk: [1,1,5], wv: [512,1,3,3]
// Output (concatenated): out [16,512,64,64], s_new [16,512,1,4096], z_new [16,1,512,1]

#define B 16
#define C 512
#define HW 4096
#define BC (B * C)            // 8192
#define OUT_ELEMS (BC * HW)   // 33554432

// Scratch (device globals; no allocation allowed)
__device__ float g_y[BC];
__device__ float g_kf[BC];
__device__ float g_coef[BC];

// ---------------------------------------------------------------------------
// Kernel 1: spatial mean of x per (b,c)
// ---------------------------------------------------------------------------
__global__ void __launch_bounds__(256) mean_kernel(const float* __restrict__ x) {
    int bc = blockIdx.x;
    const float4* xp = reinterpret_cast<const float4*>(x + (size_t)bc * HW);
    int t = threadIdx.x;
    float sum = 0.0f;
#pragma unroll
    for (int k = 0; k < 4; k++) {
        float4 v = xp[t + k * 256];
        sum += (v.x + v.y) + (v.z + v.w);
    }
#pragma unroll
    for (int o = 16; o > 0; o >>= 1) sum += __shfl_xor_sync(0xffffffffu, sum, o);
    __shared__ float ws[8];
    if ((t & 31) == 0) ws[t >> 5] = sum;
    __syncthreads();
    if (t < 8) {
        float s2 = ws[t];
#pragma unroll
        for (int o = 4; o > 0; o >>= 1) s2 += __shfl_xor_sync(0xffu, s2, o);
        if (t == 0) g_y[bc] = s2 * (1.0f / (float)HW);
    }
}

// ---------------------------------------------------------------------------
// Kernel 2: channel conv (k=5, SAME zero-pad) -> elu+1 -> Kf, coef, z_new
// ---------------------------------------------------------------------------
__global__ void qk_kernel(const float* __restrict__ z,
                          const float* __restrict__ wq,
                          const float* __restrict__ wk,
                          float* __restrict__ z_out) {
    int bc = blockIdx.x * blockDim.x + threadIdx.x;
    if (bc >= BC) return;
    int b = bc >> 9;
    int c = bc & 511;
    float q = 0.0f, k = 0.0f;
#pragma unroll
    for (int j = 0; j < 5; j++) {
        int cc = c + j - 2;
        float v = ((unsigned)cc < (unsigned)C) ? g_y[(b << 9) + cc] : 0.0f;
        q += wq[j] * v;
        k += wk[j] * v;
    }
    // elu(t)+1 : t>0 -> t+1 ; t<=0 -> exp(t)
    float Qf = (q > 0.0f) ? (q + 1.0f) : expf(q);
    float Kf = (k > 0.0f) ? (k + 1.0f) : expf(k);
    float zn = z[bc] + Kf;
    float qz = 1.0f / (Qf * (zn + 1e-6f));
    g_kf[bc] = Kf;
    g_coef[bc] = Qf * qz;   // matches reference's (Qf * qz) factor
    z_out[bc] = zn;
}

// ---------------------------------------------------------------------------
// Kernel 3: depthwise 3x3 conv (SAME) + s_new = s + Kf*V ; out = coef * s_new
// One block per (b,c). 66x66 smem halo tile. Each thread: 4 float4s.
// ---------------------------------------------------------------------------
#define TP 66   // tile pitch

__global__ void __launch_bounds__(256) main_kernel(const float* __restrict__ x,
                                                   const float* __restrict__ s,
                                                   const float* __restrict__ wv,
                                                   float* __restrict__ out,
                                                   float* __restrict__ s_new) {
    int bc = blockIdx.x;
    int c = bc & 511;
    size_t base = (size_t)bc * HW;

    __shared__ float tile[TP * TP];

    const float* xb = x + base;
    // Fill 66x66 tile with zero halo
    for (int i = threadIdx.x; i < TP * TP; i += 256) {
        int r = i / TP - 1;
        int cc = i % TP - 1;
        float v = 0.0f;
        if ((unsigned)r < 64u && (unsigned)cc < 64u) v = __ldg(xb + r * 64 + cc);
        tile[i] = v;
    }

    float w[9];
#pragma unroll
    for (int j = 0; j < 9; j++) w[j] = __ldg(wv + c * 9 + j);
    float Kf = g_kf[bc];
    float Cf = g_coef[bc];

    __syncthreads();

    const float4* sp = reinterpret_cast<const float4*>(s + base);
    float4* op = reinterpret_cast<float4*>(out + base);
    float4* np = reinterpret_cast<float4*>(s_new + base);

#pragma unroll
    for (int k = 0; k < 4; k++) {
        int q = threadIdx.x + k * 256;   // float4 index within the 4096-pixel plane
        int p = q << 2;                  // first pixel
        int r = p >> 6;
        int col0 = p & 63;

        float4 sv = sp[q];

        float acc[4];
#pragma unroll
        for (int u = 0; u < 4; u++) {
            int col = col0 + u;
            float a = 0.0f;
#pragma unroll
            for (int di = 0; di < 3; di++) {
#pragma unroll
                for (int dj = 0; dj < 3; dj++) {
                    a = fmaf(w[di * 3 + dj], tile[(r + di) * TP + col + dj], a);
                }
            }
            acc[u] = a;
        }

        float4 sn, ov;
        sn.x = sv.x + Kf * acc[0];
        sn.y = sv.y + Kf * acc[1];
        sn.z = sv.z + Kf * acc[2];
        sn.w = sv.w + Kf * acc[3];
        ov.x = Cf * sn.x;
        ov.y = Cf * sn.y;
        ov.z = Cf * sn.z;
        ov.w = Cf * sn.w;
        np[q] = sn;
        op[q] = ov;
    }
}

// ---------------------------------------------------------------------------
extern "C" void kernel_launch(void* const* d_in, const int* in_sizes, int n_in,
                              void* d_out, int out_size) {
    const float* x  = (const float*)d_in[0];
    const float* s  = (const float*)d_in[1];
    const float* z  = (const float*)d_in[2];
    const float* wq = (const float*)d_in[3];
    const float* wk = (const float*)d_in[4];
    const float* wv = (const float*)d_in[5];

    float* out   = (float*)d_out;                 // [BC, HW]
    float* s_new = out + (size_t)OUT_ELEMS;       // [BC, HW]
    float* z_new = s_new + (size_t)OUT_ELEMS;     // [BC]

    mean_kernel<<<BC, 256>>>(x);
    qk_kernel<<<BC / 256, 256>>>(z, wq, wk, z_new);
    main_kernel<<<BC, 256>>>(x, s, wv, out, s_new);
}

// round 2
// speedup vs baseline: 1.1313x; 1.1313x over previous
#include <cuda_runtime.h>
#include <cuda_bf16.h>

// Problem shape (fixed by the dataset):
//   x : [16, 512, 64, 64] f32
//   s : [16, 512, 1, 4096] f32
//   z : [16, 1, 512, 1]   f32
//   wq: [1,1,5], wk: [1,1,5], wv: [512,1,3,3]
// Output (concatenated): out [16,512,64,64], s_new [16,512,1,4096], z_new [16,1,512,1]

#define B 16
#define C 512
#define HW 4096
#define BC (B * C)            // 8192
#define OUT_ELEMS (BC * HW)   // 33554432

// Scratch (device global; no allocation allowed)
__device__ float g_y[BC];

// ---------------------------------------------------------------------------
// Kernel 1: spatial mean of x per (b,c). Default cache policy: x allocates in
// L2 so main_kernel can re-hit it.
// ---------------------------------------------------------------------------
__global__ void __launch_bounds__(256) mean_kernel(const float* __restrict__ x) {
    int bc = blockIdx.x;
    const float4* xp = reinterpret_cast<const float4*>(x + (size_t)bc * HW);
    int t = threadIdx.x;
    float sum = 0.0f;
#pragma unroll
    for (int k = 0; k < 4; k++) {
        float4 v = xp[t + k * 256];
        sum += (v.x + v.y) + (v.z + v.w);
    }
#pragma unroll
    for (int o = 16; o > 0; o >>= 1) sum += __shfl_xor_sync(0xffffffffu, sum, o);
    __shared__ float ws[8];
    if ((t & 31) == 0) ws[t >> 5] = sum;
    __syncthreads();
    if (t < 8) {
        float s2 = ws[t];
#pragma unroll
        for (int o = 4; o > 0; o >>= 1) s2 += __shfl_xor_sync(0xffu, s2, o);
        if (t == 0) g_y[bc] = s2 * (1.0f / (float)HW);
    }
}

// ---------------------------------------------------------------------------
// Kernel 2 (fused): per-block Qf/Kf/coef/z_new + depthwise 3x3 conv +
//   s_new = s + Kf*V ; out = coef * s_new
// One block per (b,c), REVERSED order so the x planes most recently cached in
// L2 by mean_kernel are consumed first. s/out/s_new use streaming hints so
// they don't evict x from L2.
// ---------------------------------------------------------------------------
#define TP 68   // tile pitch (66 rows used; pitch 68 keeps float4 alignment)

__global__ void __launch_bounds__(256) main_kernel(const float* __restrict__ x,
                                                   const float* __restrict__ s,
                                                   const float* __restrict__ z,
                                                   const float* __restrict__ wq,
                                                   const float* __restrict__ wk,
                                                   const float* __restrict__ wv,
                                                   float* __restrict__ out,
                                                   float* __restrict__ s_new,
                                                   float* __restrict__ z_new) {
    int bc = (BC - 1) - (int)blockIdx.x;   // reversed plane order (L2 MRU-first)
    int b = bc >> 9;
    int c = bc & 511;
    size_t base = (size_t)bc * HW;

    __shared__ float tile[66 * TP];
    __shared__ float sKf, sCf;

    // Thread 0: channel conv (k=5, SAME) -> elu+1 -> Kf, coef, z_new
    if (threadIdx.x == 0) {
        float q = 0.0f, k = 0.0f;
#pragma unroll
        for (int j = 0; j < 5; j++) {
            int cc = c + j - 2;
            float v = ((unsigned)cc < (unsigned)C) ? g_y[(b << 9) + cc] : 0.0f;
            q += __ldg(wq + j) * v;
            k += __ldg(wk + j) * v;
        }
        float Qf = (q > 0.0f) ? (q + 1.0f) : expf(q);
        float Kf = (k > 0.0f) ? (k + 1.0f) : expf(k);
        float zn = z[bc] + Kf;
        float qz = 1.0f / (Qf * (zn + 1e-6f));
        sKf = Kf;
        sCf = Qf * qz;
        z_new[bc] = zn;
    }

    // Fill 66x66 halo tile (pitch 68). x read is streaming (last use).
    const float* xb = x + base;
    for (int i = threadIdx.x; i < 66 * 66; i += 256) {
        int rr = i / 66;        // 0..65 (halo row)
        int cc = i - rr * 66;   // 0..65 (halo col)
        float v = 0.0f;
        if ((unsigned)(rr - 1) < 64u && (unsigned)(cc - 1) < 64u)
            v = __ldcs(xb + (rr - 1) * 64 + (cc - 1));
        tile[rr * TP + cc] = v;
    }

    float w[9];
#pragma unroll
    for (int j = 0; j < 9; j++) w[j] = __ldg(wv + c * 9 + j);

    __syncthreads();

    float Kf = sKf;
    float Cf = sCf;

    const float4* sp = reinterpret_cast<const float4*>(s + base);
    float4* op = reinterpret_cast<float4*>(out + base);
    float4* np = reinterpret_cast<float4*>(s_new + base);

#pragma unroll
    for (int k = 0; k < 4; k++) {
        int q = threadIdx.x + k * 256;   // float4 index within the 4096-pixel plane
        int p = q << 2;                  // first pixel
        int r = p >> 6;                  // output row 0..63
        int col0 = p & 63;               // output col (multiple of 4)

        float4 sv = __ldcs(sp + q);      // streaming: don't pollute L2

        float a0 = 0.0f, a1 = 0.0f, a2 = 0.0f, a3 = 0.0f;
#pragma unroll
        for (int di = 0; di < 3; di++) {
            const float* rowp = &tile[(r + di) * TP + col0];
            float4 f4 = *reinterpret_cast<const float4*>(rowp);      // 16B aligned
            float2 f2 = *reinterpret_cast<const float2*>(rowp + 4);  // 8B aligned
            float w0 = w[di * 3 + 0], w1 = w[di * 3 + 1], w2 = w[di * 3 + 2];
            a0 = fmaf(w0, f4.x, fmaf(w1, f4.y, fmaf(w2, f4.z, a0)));
            a1 = fmaf(w0, f4.y, fmaf(w1, f4.z, fmaf(w2, f4.w, a1)));
            a2 = fmaf(w0, f4.z, fmaf(w1, f4.w, fmaf(w2, f2.x, a2)));
            a3 = fmaf(w0, f4.w, fmaf(w1, f2.x, fmaf(w2, f2.y, a3)));
        }

        float4 sn, ov;
        sn.x = sv.x + Kf * a0;
        sn.y = sv.y + Kf * a1;
        sn.z = sv.z + Kf * a2;
        sn.w = sv.w + Kf * a3;
        ov.x = Cf * sn.x;
        ov.y = Cf * sn.y;
        ov.z = Cf * sn.z;
        ov.w = Cf * sn.w;
        __stcs(np + q, sn);   // streaming stores: keep L2 for x
        __stcs(op + q, ov);
    }
}

// ---------------------------------------------------------------------------
extern "C" void kernel_launch(void* const* d_in, const int* in_sizes, int n_in,
                              void* d_out, int out_size) {
    const float* x  = (const float*)d_in[0];
    const float* s  = (const float*)d_in[1];
    const float* z  = (const float*)d_in[2];
    const float* wq = (const float*)d_in[3];
    const float* wk = (const float*)d_in[4];
    const float* wv = (const float*)d_in[5];

    float* out   = (float*)d_out;                 // [BC, HW]
    float* s_new = out + (size_t)OUT_ELEMS;       // [BC, HW]
    float* z_new = s_new + (size_t)OUT_ELEMS;     // [BC]

    mean_kernel<<<BC, 256>>>(x);
    main_kernel<<<BC, 256>>>(x, s, z, wq, wk, wv, out, s_new, z_new);
}

// round 5
// speedup vs baseline: 1.3681x; 1.2093x over previous
#include <cuda_runtime.h>
#include <cuda_bf16.h>

// Problem shape (fixed by the dataset):
//   x : [16, 512, 64, 64] f32
//   s : [16, 512, 1, 4096] f32
//   z : [16, 1, 512, 1]   f32
//   wq: [1,1,5], wk: [1,1,5], wv: [512,1,3,3]
// Output: out [16,512,64,64], s_new [16,512,1,4096], z_new [16,1,512,1]

#define B 16
#define C 512
#define HW 4096
#define BC (B * C)            // 8192
#define OUT_ELEMS (BC * HW)   // 33554432

__device__ float g_y[BC];

// ---------------------------------------------------------------------------
// Kernel 1: spatial mean of x per (b,c). Default cache policy so x lands in L2.
// ---------------------------------------------------------------------------
__global__ void __launch_bounds__(256) mean_kernel(const float* __restrict__ x) {
    int bc = blockIdx.x;
    const float4* xp = reinterpret_cast<const float4*>(x + (size_t)bc * HW);
    int t = threadIdx.x;
    float sum = 0.0f;
#pragma unroll
    for (int k = 0; k < 4; k++) {
        float4 v = xp[t + k * 256];
        sum += (v.x + v.y) + (v.z + v.w);
    }
#pragma unroll
    for (int o = 16; o > 0; o >>= 1) sum += __shfl_xor_sync(0xffffffffu, sum, o);
    __shared__ float ws[8];
    if ((t & 31) == 0) ws[t >> 5] = sum;
    __syncthreads();
    if (t < 8) {
        float s2 = ws[t];
#pragma unroll
        for (int o = 4; o > 0; o >>= 1) s2 += __shfl_xor_sync(0xffu, s2, o);
        if (t == 0) g_y[bc] = s2 * (1.0f / (float)HW);
    }
}

// ---------------------------------------------------------------------------
// Kernel 2 (fused): Qf/Kf/coef/z_new + depthwise 3x3 conv + epilogue.
// Fully vectorized loads; halo tile; reversed block order for L2 x-reuse.
// ---------------------------------------------------------------------------
#define TP 68   // tile pitch: 66 rows x 68 floats; (r*68 + col0) % 4 == 0

__global__ void __launch_bounds__(256) main_kernel(const float* __restrict__ x,
                                                   const float* __restrict__ s,
                                                   const float* __restrict__ z,
                                                   const float* __restrict__ wq,
                                                   const float* __restrict__ wk,
                                                   const float* __restrict__ wv,
                                                   float* __restrict__ out,
                                                   float* __restrict__ s_new,
                                                   float* __restrict__ z_new) {
    int bc = (BC - 1) - (int)blockIdx.x;   // reversed: consume L2 MRU planes first
    int b = bc >> 9;
    int c = bc & 511;
    size_t base = (size_t)bc * HW;
    int t = threadIdx.x;

    __shared__ float tile[66 * TP];
    __shared__ float sKf, sCf;

    // Front-batched vector loads: 4x x + 4x s = 8 LDG.128 in flight per thread.
    const float4* xp = reinterpret_cast<const float4*>(x + base);
    const float4* sp = reinterpret_cast<const float4*>(s + base);
    float4 xa[4], sv[4];
#pragma unroll
    for (int k = 0; k < 4; k++) xa[k] = __ldcs(xp + t + k * 256);
#pragma unroll
    for (int k = 0; k < 4; k++) sv[k] = __ldcs(sp + t + k * 256);

    // Zero the halo ring (260 floats) while loads are in flight.
    if (t < 66) { tile[t] = 0.0f; tile[65 * TP + t] = 0.0f; }
    if (t < 64) { tile[(t + 1) * TP] = 0.0f; tile[(t + 1) * TP + 65] = 0.0f; }

    // Per-channel weights.
    float w[9];
#pragma unroll
    for (int j = 0; j < 9; j++) w[j] = __ldg(wv + c * 9 + j);

    // Thread 0: channel conv (k=5, SAME) -> elu+1 -> Kf, coef, z_new.
    if (t == 0) {
        float q = 0.0f, k = 0.0f;
#pragma unroll
        for (int j = 0; j < 5; j++) {
            int cc = c + j - 2;
            float v = ((unsigned)cc < (unsigned)C) ? g_y[(b << 9) + cc] : 0.0f;
            q += __ldg(wq + j) * v;
            k += __ldg(wk + j) * v;
        }
        float Qf = (q > 0.0f) ? (q + 1.0f) : expf(q);
        float Kf = (k > 0.0f) ? (k + 1.0f) : expf(k);
        float zn = z[bc] + Kf;
        float qz = 1.0f / (Qf * (zn + 1e-6f));
        sKf = Kf;
        sCf = Qf * qz;
        z_new[bc] = zn;
    }

    // Scatter x into the haloed tile (interior only; no predication, no division).
#pragma unroll
    for (int k = 0; k < 4; k++) {
        int q = t + k * 256;          // float4 index 0..1023
        int p = q << 2;               // pixel
        int r = p >> 6;               // row 0..63
        int col = p & 63;             // col (multiple of 4)
        float* dst = &tile[(r + 1) * TP + col + 1];
        dst[0] = xa[k].x; dst[1] = xa[k].y; dst[2] = xa[k].z; dst[3] = xa[k].w;
    }
    __syncthreads();

    float Kf = sKf;
    float Cf = sCf;

    float4* op = reinterpret_cast<float4*>(out + base);
    float4* np = reinterpret_cast<float4*>(s_new + base);

#pragma unroll
    for (int k = 0; k < 4; k++) {
        int q = t + k * 256;
        int p = q << 2;
        int r = p >> 6;
        int col0 = p & 63;

        float a0 = 0.0f, a1 = 0.0f, a2 = 0.0f, a3 = 0.0f;
#pragma unroll
        for (int di = 0; di < 3; di++) {
            // tile row (r+di), halo cols col0 .. col0+5  (base aligned to 16B)
            const float* rowp = &tile[(r + di) * TP + col0];
            float4 f4 = *reinterpret_cast<const float4*>(rowp);
            float2 f2 = *reinterpret_cast<const float2*>(rowp + 4);
            float w0 = w[di * 3 + 0], w1 = w[di * 3 + 1], w2 = w[di * 3 + 2];
            a0 = fmaf(w0, f4.x, fmaf(w1, f4.y, fmaf(w2, f4.z, a0)));
            a1 = fmaf(w0, f4.y, fmaf(w1, f4.z, fmaf(w2, f4.w, a1)));
            a2 = fmaf(w0, f4.z, fmaf(w1, f4.w, fmaf(w2, f2.x, a2)));
            a3 = fmaf(w0, f4.w, fmaf(w1, f2.x, fmaf(w2, f2.y, a3)));
        }

        float4 sn, ov;
        sn.x = sv[k].x + Kf * a0;
        sn.y = sv[k].y + Kf * a1;
        sn.z = sv[k].z + Kf * a2;
        sn.w = sv[k].w + Kf * a3;
        ov.x = Cf * sn.x;
        ov.y = Cf * sn.y;
        ov.z = Cf * sn.z;
        ov.w = Cf * sn.w;
        __stcs(np + q, sn);
        __stcs(op + q, ov);
    }
}

// ---------------------------------------------------------------------------
extern "C" void kernel_launch(void* const* d_in, const int* in_sizes, int n_in,
                              void* d_out, int out_size) {
    const float* x  = (const float*)d_in[0];
    const float* s  = (const float*)d_in[1];
    const float* z  = (const float*)d_in[2];
    const float* wq = (const float*)d_in[3];
    const float* wk = (const float*)d_in[4];
    const float* wv = (const float*)d_in[5];

    float* out   = (float*)d_out;                 // [BC, HW]
    float* s_new = out + (size_t)OUT_ELEMS;       // [BC, HW]
    float* z_new = s_new + (size_t)OUT_ELEMS;     // [BC]

    mean_kernel<<<BC, 256>>>(x);
    main_kernel<<<BC, 256>>>(x, s, z, wq, wk, wv, out, s_new, z_new);
}